// round 3
// baseline (speedup 1.0000x reference)
#include <cuda_runtime.h>
#include <cuda_bf16.h>

// Problem constants (FilterDetections: B=4, N=49104, C=90)
#define NB 4
#define NA 49104
#define NC 90
#define MAXDET 100
#define NEGV (-1e30f)
#define SCORE_THR 0.01f
#define IOU_THR 0.1f

#define T1 1024
#define IPT 48            // 48 * 1024 = 49152 >= 49104

#define T2 1024
#define TOT (NC * MAXDET) // 9000
#define IPT2 9            // 9 * 1024 = 9216 >= 9000

// Scratch: kept detections per (image, class)
__device__ float g_ks[NB * NC * MAXDET];
__device__ int   g_ka[NB * NC * MAXDET];
__device__ int   g_kc[NB * NC];

// ---------------------------------------------------------------------------
// Phase 1: greedy per-class NMS. One CTA per (b, c) pair.
// Scores live in registers (NEG sentinel = filtered/suppressed/selected).
// ---------------------------------------------------------------------------
__global__ __launch_bounds__(T1) void nms_kernel(const float* __restrict__ boxes,
                                                 const float* __restrict__ cls)
{
    const int pair = blockIdx.x;
    const int b = pair / NC;
    const int c = pair % NC;
    const float4* __restrict__ bb = (const float4*)(boxes + (size_t)b * NA * 4);
    const float* __restrict__ sc = cls + (size_t)b * NA * NC + c;
    const int t = threadIdx.x;

    // Load + threshold scores into registers
    float s[IPT];
#pragma unroll
    for (int i = 0; i < IPT; i++) {
        int a = i * T1 + t;
        float v = (a < NA) ? sc[(size_t)a * NC] : NEGV;
        s[i] = (v > SCORE_THR) ? v : NEGV;
    }

    __shared__ float wv[32];
    __shared__ int   wi[32];
    __shared__ float sbox[4];
    __shared__ int   ssel;
    __shared__ float ks_s[MAXDET];
    __shared__ int   ka_s[MAXDET];
    __shared__ int   scnt;
    if (t == 0) scnt = 0;

    bool exhausted = false;

    for (int it = 0; it < MAXDET; it++) {
        // ---- local argmax (ties -> lowest anchor index, matching jnp.argmax)
        float bv = NEGV;
        int   bi = 0x7FFFFFFF;
#pragma unroll
        for (int i = 0; i < IPT; i++) {
            if (s[i] > bv) { bv = s[i]; bi = i * T1 + t; }
        }
        // ---- warp reduce
#pragma unroll
        for (int o = 16; o; o >>= 1) {
            float ov = __shfl_down_sync(0xffffffffu, bv, o);
            int   oi = __shfl_down_sync(0xffffffffu, bi, o);
            if (ov > bv || (ov == bv && oi < bi)) { bv = ov; bi = oi; }
        }
        if ((t & 31) == 0) { wv[t >> 5] = bv; wi[t >> 5] = bi; }
        __syncthreads();
        // ---- block reduce (warp 0)
        if (t < 32) {
            bv = wv[t]; bi = wi[t];
#pragma unroll
            for (int o = 16; o; o >>= 1) {
                float ov = __shfl_down_sync(0xffffffffu, bv, o);
                int   oi = __shfl_down_sync(0xffffffffu, bi, o);
                if (ov > bv || (ov == bv && oi < bi)) { bv = ov; bi = oi; }
            }
            if (t == 0) {
                if (bv > -0.5e30f) {
                    float4 bx = bb[bi];
                    sbox[0] = bx.x; sbox[1] = bx.y; sbox[2] = bx.z; sbox[3] = bx.w;
                    ssel = bi;
                    int k = scnt;
                    ks_s[k] = bv;
                    ka_s[k] = bi;
                    scnt = k + 1;
                } else {
                    ssel = -1;
                }
            }
        }
        __syncthreads();

        int sel = ssel;
        if (sel < 0) { exhausted = true; break; }

        // ---- suppression pass: IOU of selected box vs all still-active anchors
        float y1 = sbox[0], x1 = sbox[1], y2 = sbox[2], x2 = sbox[3];
        float sarea = (y2 - y1) * (x2 - x1);
#pragma unroll
        for (int i = 0; i < IPT; i++) {
            if (s[i] > -1e29f) {
                int a = i * T1 + t;
                float4 bx = bb[a];
                float iy1 = fmaxf(y1, bx.x);
                float ix1 = fmaxf(x1, bx.y);
                float iy2 = fminf(y2, bx.z);
                float ix2 = fminf(x2, bx.w);
                float inter = fmaxf(iy2 - iy1, 0.0f) * fmaxf(ix2 - ix1, 0.0f);
                float barea = (bx.z - bx.x) * (bx.w - bx.y);
                float iou = inter / (sarea + barea - inter + 1e-8f);
                if (iou > IOU_THR) s[i] = NEGV;
                if (a == sel)      s[i] = NEGV;  // selected always cleared
            }
        }
        __syncthreads();  // protect sbox/ssel/wv for next iteration
    }

    __syncthreads();
    if (t == 0) {
        int cnt = scnt;
        // Reference quirk: after exhaustion, jnp.argmax over all-NEG returns 0
        // and keep.at[0].set(False) un-keeps anchor 0 if it was selected.
        if (exhausted) {
            for (int k = 0; k < cnt; k++) {
                if (ka_s[k] == 0) {
                    cnt--;
                    ks_s[k] = ks_s[cnt];
                    ka_s[k] = ka_s[cnt];
                    break;
                }
            }
            scnt = cnt;
        }
    }
    __syncthreads();
    int cnt = scnt;
    int base = pair * MAXDET;
    if (t < cnt) {
        g_ks[base + t] = ks_s[t];
        g_ka[base + t] = ka_s[t];
    }
    if (t == 0) g_kc[pair] = cnt;
}

// ---------------------------------------------------------------------------
// Phase 2: per-image top-100 over all kept (anchor, class) detections.
// Matches jax.lax.top_k tie-break: value desc, flat index (anchor*C+c) asc.
// One CTA per image; candidate values live in registers.
// ---------------------------------------------------------------------------
__global__ __launch_bounds__(T2) void topk_kernel(const float* __restrict__ boxes,
                                                  float* __restrict__ out)
{
    const int b = blockIdx.x;
    const int t = threadIdx.x;

    __shared__ int cnts[NC];
    if (t < NC) cnts[t] = g_kc[b * NC + t];
    __syncthreads();

    // Load candidates into registers
    float val[IPT2];
    int   flt[IPT2];
#pragma unroll
    for (int i = 0; i < IPT2; i++) {
        int slot = i * T2 + t;
        val[i] = NEGV;
        flt[i] = 0x7FFFFFFF;
        if (slot < TOT) {
            int c = slot / MAXDET;
            int j = slot % MAXDET;
            if (j < cnts[c]) {
                val[i] = g_ks[(size_t)b * TOT + slot];
                flt[i] = g_ka[(size_t)b * TOT + slot] * NC + c;
            }
        }
    }

    __shared__ float wv[32];
    __shared__ int   wf[32];
    __shared__ int   ws[32];
    __shared__ int   bslot_sh;

    const float4* __restrict__ bb = (const float4*)(boxes + (size_t)b * NA * 4);
    float* ob = out + (size_t)b * MAXDET * 4;
    float* os = out + (size_t)NB * MAXDET * 4 + (size_t)b * MAXDET;
    float* ol = out + (size_t)NB * MAXDET * 5 + (size_t)b * MAXDET;

    for (int k = 0; k < MAXDET; k++) {
        float bv = NEGV;
        int   bf = 0x7FFFFFFF;
        int   bs = -1;
#pragma unroll
        for (int i = 0; i < IPT2; i++) {
            if (val[i] > bv || (val[i] == bv && flt[i] < bf)) {
                bv = val[i]; bf = flt[i]; bs = i * T2 + t;
            }
        }
#pragma unroll
        for (int o = 16; o; o >>= 1) {
            float ov = __shfl_down_sync(0xffffffffu, bv, o);
            int   of = __shfl_down_sync(0xffffffffu, bf, o);
            int   osl = __shfl_down_sync(0xffffffffu, bs, o);
            if (ov > bv || (ov == bv && of < bf)) { bv = ov; bf = of; bs = osl; }
        }
        if ((t & 31) == 0) { wv[t >> 5] = bv; wf[t >> 5] = bf; ws[t >> 5] = bs; }
        __syncthreads();
        if (t < 32) {
            bv = wv[t]; bf = wf[t]; bs = ws[t];
#pragma unroll
            for (int o = 16; o; o >>= 1) {
                float ov = __shfl_down_sync(0xffffffffu, bv, o);
                int   of = __shfl_down_sync(0xffffffffu, bf, o);
                int   osl = __shfl_down_sync(0xffffffffu, bs, o);
                if (ov > bv || (ov == bv && of < bf)) { bv = ov; bf = of; bs = osl; }
            }
            if (t == 0) {
                if (bv > -0.5e30f) {
                    int anchor = bf / NC;
                    int lab = bf - anchor * NC;
                    float4 bx = bb[anchor];
                    ob[k * 4 + 0] = bx.x;
                    ob[k * 4 + 1] = bx.y;
                    ob[k * 4 + 2] = bx.z;
                    ob[k * 4 + 3] = bx.w;
                    os[k] = bv;
                    ol[k] = (float)lab;
                    bslot_sh = bs;
                } else {
                    ob[k * 4 + 0] = -1.0f;
                    ob[k * 4 + 1] = -1.0f;
                    ob[k * 4 + 2] = -1.0f;
                    ob[k * 4 + 3] = -1.0f;
                    os[k] = -1.0f;
                    ol[k] = -1.0f;
                    bslot_sh = -1;
                }
            }
        }
        __syncthreads();
        int bsel = bslot_sh;
        if (bsel >= 0) {
            // Owner thread clears its selected slot
            if ((bsel & (T2 - 1)) == t) {
                int i = bsel >> 10;  // T2 = 1024
#pragma unroll
                for (int ii = 0; ii < IPT2; ii++) {
                    if (ii == i) { val[ii] = NEGV; flt[ii] = 0x7FFFFFFF; }
                }
            }
        }
        __syncthreads();
    }
}

extern "C" void kernel_launch(void* const* d_in, const int* in_sizes, int n_in,
                              void* d_out, int out_size)
{
    const float* boxes = (const float*)d_in[0];
    const float* cls   = (const float*)d_in[1];
    float* out = (float*)d_out;

    nms_kernel<<<NB * NC, T1>>>(boxes, cls);
    topk_kernel<<<NB, T2>>>(boxes, out);
}

// round 4
// speedup vs baseline: 9.6886x; 9.6886x over previous
#include <cuda_runtime.h>
#include <cuda_bf16.h>

typedef unsigned long long u64;
typedef unsigned int u32;

#define NB 4
#define NA 49104
#define NC 90
#define MAXDET 100
#define NPAIR (NB * NC)
#define NEGV (-1e30f)
#define SCORE_THR 0.01f
#define IOU_THR 0.1f

// Candidate prefix: scores > T0 (uniform data -> ~4910 per pair, 18+ sigma below CAP)
#define T0 0.90f
#define CAP 6144
#define NBIN 2048
#define PREF 2048
#define TF 512

// Fallback (R2 full-NMS) config
#define T1 1024
#define IPT 48

// ---------------- global scratch ----------------
__device__ u64  g_cand[(size_t)NPAIR * CAP];
__device__ int  g_cnt[NPAIR];
__device__ int  g_flag[NPAIR];
__device__ float g_ks[NPAIR * MAXDET];
__device__ int   g_ka[NPAIR * MAXDET];
__device__ int   g_kc[NPAIR];

// ---------------------------------------------------------------------------
__global__ void init_kernel()
{
    int t = threadIdx.x;
    if (t < NPAIR) { g_cnt[t] = 0; g_flag[t] = 0; }
}

// ---------------------------------------------------------------------------
// Gather: compact candidates with score > T0 per (b,c). CTA per (image, 8-class
// group) so one L2 sector feeds 8 classes.
// ---------------------------------------------------------------------------
__global__ __launch_bounds__(TF) void gather_kernel(const float* __restrict__ cls)
{
    const int b = blockIdx.y;
    const int c0 = blockIdx.x * 8;
    const float* __restrict__ base = cls + (size_t)b * NA * NC;

    for (int a = threadIdx.x; a < NA; a += TF) {
        const float* row = base + (size_t)a * NC + c0;
#pragma unroll
        for (int j = 0; j < 8; j++) {
            int c = c0 + j;
            if (c >= NC) break;
            float s = row[j];
            if (s > T0) {
                int pair = b * NC + c;
                int pos = atomicAdd(&g_cnt[pair], 1);
                if (pos < CAP) {
                    u64 key = ((u64)__float_as_uint(s) << 32) |
                              (u32)(0xFFFFFFFFu - (u32)a);
                    g_cand[(size_t)pair * CAP + pos] = key;
                }
            }
        }
    }
}

// ---------------------------------------------------------------------------
// Fused: counting-sort candidates (desc by (score, anchor asc)) + warp-batched
// greedy NMS. One CTA per pair. Flags fallback if prefix insufficient.
// ---------------------------------------------------------------------------
#define DYN_BYTES (CAP * 8 + PREF * 16 + NBIN * 4 * 2)

__global__ __launch_bounds__(TF, 2) void fused_kernel(const float* __restrict__ boxes)
{
    const int pair = blockIdx.x;
    const int b = pair / NC;
    const float4* __restrict__ bb = (const float4*)(boxes + (size_t)b * NA * 4);
    const int t = threadIdx.x;

    extern __shared__ char dyn[];
    u64*    skey     = (u64*)dyn;                           // CAP * 8
    float4* sbox     = (float4*)(dyn + CAP * 8);            // PREF * 16
    u32*    binstart = (u32*)(dyn + CAP * 8 + PREF * 16);   // NBIN * 4
    u32*    bincnt   = binstart + NBIN;                     // NBIN * 4

    __shared__ float4 kb[MAXDET];
    __shared__ float  karea[MAXDET];
    __shared__ float  ksc[MAXDET];
    __shared__ int    kan[MAXDET];
    __shared__ u32    warpsum[16];
    __shared__ int    s_kept, s_done;

    int cnt = g_cnt[pair];
    if (cnt > CAP) { if (t == 0) g_flag[pair] = 1; return; }
    if (cnt < 0) cnt = 0;

    for (int i = t; i < NBIN; i += TF) bincnt[i] = 0;
    __syncthreads();

    const u64* __restrict__ cand = &g_cand[(size_t)pair * CAP];

    // histogram (binning monotonic in score; flipped for descending order)
    for (int i = t; i < cnt; i += TF) {
        u64 k = cand[i];
        float s = __uint_as_float((u32)(k >> 32));
        int bin = (int)((s - T0) * 20480.0f);
        bin = min(max(bin, 0), NBIN - 1);
        atomicAdd(&bincnt[NBIN - 1 - bin], 1u);
    }
    __syncthreads();

    // exclusive scan over NBIN bins (4 bins/thread)
    {
        u32 c0_ = bincnt[4 * t], c1_ = bincnt[4 * t + 1];
        u32 c2_ = bincnt[4 * t + 2], c3_ = bincnt[4 * t + 3];
        u32 tsum = c0_ + c1_ + c2_ + c3_;
        u32 lane = t & 31, w = t >> 5;
        u32 x = tsum;
#pragma unroll
        for (int o = 1; o < 32; o <<= 1) {
            u32 y = __shfl_up_sync(0xffffffffu, x, o);
            if (lane >= (u32)o) x += y;
        }
        if (lane == 31) warpsum[w] = x;
        __syncthreads();
        if (t == 0) {
            u32 r = 0;
#pragma unroll
            for (int i2 = 0; i2 < 16; i2++) { u32 v = warpsum[i2]; warpsum[i2] = r; r += v; }
        }
        __syncthreads();
        u32 ex = warpsum[w] + x - tsum;
        binstart[4 * t + 0] = ex;
        binstart[4 * t + 1] = ex + c0_;
        binstart[4 * t + 2] = ex + c0_ + c1_;
        binstart[4 * t + 3] = ex + c0_ + c1_ + c2_;
    }
    __syncthreads();

    // scatter (binstart becomes end cursor)
    for (int i = t; i < cnt; i += TF) {
        u64 k = cand[i];
        float s = __uint_as_float((u32)(k >> 32));
        int bin = (int)((s - T0) * 20480.0f);
        bin = min(max(bin, 0), NBIN - 1);
        u32 pos = atomicAdd(&binstart[NBIN - 1 - bin], 1u);
        skey[pos] = k;
    }
    __syncthreads();

    // fix within-bin order (descending u64 => score desc, anchor asc)
    for (int bin = t; bin < NBIN; bin += TF) {
        int c2 = (int)bincnt[bin];
        if (c2 >= 2) {
            int st = (int)binstart[bin] - c2;
            for (int x = st + 1; x < st + c2; x++) {
                u64 kk = skey[x];
                int y = x - 1;
                while (y >= st && skey[y] < kk) { skey[y + 1] = skey[y]; y--; }
                skey[y + 1] = kk;
            }
        }
    }
    if (t == 0) { s_kept = 0; s_done = 0; }
    __syncthreads();

    // gather boxes for first PREF candidates
    int np = min(cnt, PREF);
    for (int i = t; i < np; i += TF) {
        u32 a = 0xFFFFFFFFu - (u32)skey[i];
        sbox[i] = bb[a];
    }
    __syncthreads();

    // greedy on warp 0: batches of 32 candidates, speculative + serial fixup
    if (t < 32) {
        const int lane = t;
        int kept = 0;
        int i = 0;
        while (kept < MAXDET && i < cnt) {
            int batch = min(32, cnt - i);
            int idx = i + lane;
            bool act = lane < batch;
            float4 bx = make_float4(0.f, 0.f, 0.f, 0.f);
            float sc_ = 0.f;
            u32 anc = 0;
            if (act) {
                u64 k = skey[idx];
                sc_ = __uint_as_float((u32)(k >> 32));
                anc = 0xFFFFFFFFu - (u32)k;
                bx = (idx < PREF) ? sbox[idx] : bb[anc];
            }
            float barea = (bx.z - bx.x) * (bx.w - bx.y);
            bool ok = act;
            for (int j = 0; j < kept && ok; j++) {
                float4 s4 = kb[j];
                float iy1 = fmaxf(s4.x, bx.x);
                float ix1 = fmaxf(s4.y, bx.y);
                float iy2 = fminf(s4.z, bx.z);
                float ix2 = fminf(s4.w, bx.w);
                float inter = fmaxf(iy2 - iy1, 0.0f) * fmaxf(ix2 - ix1, 0.0f);
                float iou = inter / (karea[j] + barea - inter + 1e-8f);
                if (iou > IOU_THR) ok = false;
            }
            u32 prov = __ballot_sync(0xffffffffu, ok);
            u32 m = prov;
            while (m && kept < MAXDET) {
                int l = __ffs(m) - 1;
                m &= m - 1;
                float ay1 = __shfl_sync(0xffffffffu, bx.x, l);
                float ax1 = __shfl_sync(0xffffffffu, bx.y, l);
                float ay2 = __shfl_sync(0xffffffffu, bx.z, l);
                float ax2 = __shfl_sync(0xffffffffu, bx.w, l);
                float asc = __shfl_sync(0xffffffffu, sc_, l);
                u32   aan = __shfl_sync(0xffffffffu, anc, l);
                float aarea = (ay2 - ay1) * (ax2 - ax1);
                if (lane == 0) {
                    kb[kept] = make_float4(ay1, ax1, ay2, ax2);
                    karea[kept] = aarea;
                    ksc[kept] = asc;
                    kan[kept] = (int)aan;
                }
                __syncwarp();
                kept++;
                if (kept >= MAXDET) break;
                // test later provisional candidates vs this accept
                bool fail = false;
                if (((prov >> lane) & 1u) && lane > l) {
                    float iy1 = fmaxf(ay1, bx.x);
                    float ix1 = fmaxf(ax1, bx.y);
                    float iy2 = fminf(ay2, bx.z);
                    float ix2 = fminf(ax2, bx.w);
                    float inter = fmaxf(iy2 - iy1, 0.0f) * fmaxf(ix2 - ix1, 0.0f);
                    float iou = inter / (aarea + barea - inter + 1e-8f);
                    if (iou > IOU_THR) fail = true;
                }
                u32 fm = __ballot_sync(0xffffffffu, fail);
                prov &= ~fm;
                m &= ~fm;
            }
            __syncwarp();
            i += batch;
        }
        if (lane == 0) { s_kept = kept; s_done = (kept >= MAXDET); }
    }
    __syncthreads();

    if (!s_done) { if (t == 0) g_flag[pair] = 1; return; }

    int kept = s_kept;
    if (t < kept) {
        g_ks[pair * MAXDET + t] = ksc[t];
        g_ka[pair * MAXDET + t] = kan[t];
    }
    if (t == 0) g_kc[pair] = kept;
}

// ---------------------------------------------------------------------------
// Fallback: full per-pair NMS (R2 kernel), runs only for flagged pairs.
// Order-preserving exhaustion-quirk handling (keeps list score-descending).
// ---------------------------------------------------------------------------
__global__ __launch_bounds__(T1) void fallback_kernel(const float* __restrict__ boxes,
                                                      const float* __restrict__ cls)
{
    const int pair = blockIdx.x;
    if (!g_flag[pair]) return;
    const int b = pair / NC;
    const int c = pair % NC;
    const float4* __restrict__ bb = (const float4*)(boxes + (size_t)b * NA * 4);
    const float* __restrict__ sc = cls + (size_t)b * NA * NC + c;
    const int t = threadIdx.x;

    float s[IPT];
#pragma unroll
    for (int i = 0; i < IPT; i++) {
        int a = i * T1 + t;
        float v = (a < NA) ? sc[(size_t)a * NC] : NEGV;
        s[i] = (v > SCORE_THR) ? v : NEGV;
    }

    __shared__ float wv[32];
    __shared__ int   wi[32];
    __shared__ float sbox[4];
    __shared__ int   ssel;
    __shared__ float ks_s[MAXDET];
    __shared__ int   ka_s[MAXDET];
    __shared__ int   scnt;
    if (t == 0) scnt = 0;

    bool exhausted = false;

    for (int it = 0; it < MAXDET; it++) {
        float bv = NEGV;
        int   bi = 0x7FFFFFFF;
#pragma unroll
        for (int i = 0; i < IPT; i++) {
            if (s[i] > bv) { bv = s[i]; bi = i * T1 + t; }
        }
#pragma unroll
        for (int o = 16; o; o >>= 1) {
            float ov = __shfl_down_sync(0xffffffffu, bv, o);
            int   oi = __shfl_down_sync(0xffffffffu, bi, o);
            if (ov > bv || (ov == bv && oi < bi)) { bv = ov; bi = oi; }
        }
        if ((t & 31) == 0) { wv[t >> 5] = bv; wi[t >> 5] = bi; }
        __syncthreads();
        if (t < 32) {
            bv = wv[t]; bi = wi[t];
#pragma unroll
            for (int o = 16; o; o >>= 1) {
                float ov = __shfl_down_sync(0xffffffffu, bv, o);
                int   oi = __shfl_down_sync(0xffffffffu, bi, o);
                if (ov > bv || (ov == bv && oi < bi)) { bv = ov; bi = oi; }
            }
            if (t == 0) {
                if (bv > -0.5e30f) {
                    float4 bx = bb[bi];
                    sbox[0] = bx.x; sbox[1] = bx.y; sbox[2] = bx.z; sbox[3] = bx.w;
                    ssel = bi;
                    int k = scnt;
                    ks_s[k] = bv;
                    ka_s[k] = bi;
                    scnt = k + 1;
                } else {
                    ssel = -1;
                }
            }
        }
        __syncthreads();

        int sel = ssel;
        if (sel < 0) { exhausted = true; break; }

        float y1 = sbox[0], x1 = sbox[1], y2 = sbox[2], x2 = sbox[3];
        float sarea = (y2 - y1) * (x2 - x1);
#pragma unroll
        for (int i = 0; i < IPT; i++) {
            if (s[i] > -1e29f) {
                int a = i * T1 + t;
                float4 bx = bb[a];
                float iy1 = fmaxf(y1, bx.x);
                float ix1 = fmaxf(x1, bx.y);
                float iy2 = fminf(y2, bx.z);
                float ix2 = fminf(x2, bx.w);
                float inter = fmaxf(iy2 - iy1, 0.0f) * fmaxf(ix2 - ix1, 0.0f);
                float barea = (bx.z - bx.x) * (bx.w - bx.y);
                float iou = inter / (sarea + barea - inter + 1e-8f);
                if (iou > IOU_THR) s[i] = NEGV;
                if (a == sel)      s[i] = NEGV;
            }
        }
        __syncthreads();
    }

    __syncthreads();
    if (t == 0) {
        int cnt = scnt;
        if (exhausted) {
            for (int k = 0; k < cnt; k++) {
                if (ka_s[k] == 0) {
                    for (int m2 = k; m2 < cnt - 1; m2++) {
                        ks_s[m2] = ks_s[m2 + 1];
                        ka_s[m2] = ka_s[m2 + 1];
                    }
                    cnt--;
                    break;
                }
            }
            scnt = cnt;
        }
    }
    __syncthreads();
    int cnt = scnt;
    int base2 = pair * MAXDET;
    if (t < cnt) {
        g_ks[base2 + t] = ks_s[t];
        g_ka[base2 + t] = ka_s[t];
    }
    if (t == 0) g_kc[pair] = cnt;
}

// ---------------------------------------------------------------------------
// topk: 90-way merge of sorted kept lists. 1 CTA per image, merge on warp 0.
// Key = (scorebits << 32) | (0xFFFFFFFF - flat)  => (score desc, flat asc).
// ---------------------------------------------------------------------------
#define TT 256
#define TOPK_DYN (NC * MAXDET * 8)

__global__ __launch_bounds__(TT) void topk_kernel(const float* __restrict__ boxes,
                                                  float* __restrict__ out)
{
    const int b = blockIdx.x;
    const int t = threadIdx.x;

    extern __shared__ u64 skey[];   // NC*MAXDET

    __shared__ int   cnts[NC];
    __shared__ int   w_an[MAXDET];
    __shared__ float w_sc[MAXDET];
    __shared__ int   w_lab[MAXDET];
    __shared__ int   s_nw;

    if (t < NC) cnts[t] = g_kc[b * NC + t];
    __syncthreads();

    for (int i = t; i < NC * MAXDET; i += TT) {
        int c = i / MAXDET, j = i % MAXDET;
        u64 key = 0ull;
        if (j < cnts[c]) {
            int pb = (b * NC + c) * MAXDET + j;
            float sv = g_ks[pb];
            int   av = g_ka[pb];
            u32 flat = (u32)av * NC + (u32)c;
            key = ((u64)__float_as_uint(sv) << 32) | (0xFFFFFFFFu - flat);
        }
        skey[i] = key;
    }
    __syncthreads();

    if (t < 32) {
        const int lane = t;
        u64 hk[3];
        int hj[3];
#pragma unroll
        for (int q = 0; q < 3; q++) {
            int c = lane + q * 32;
            hj[q] = 0;
            hk[q] = (c < NC) ? skey[c * MAXDET] : 0ull;
        }
        int nw = MAXDET;
        for (int k = 0; k < MAXDET; k++) {
            u64 bvk = hk[0];
            int bq = 0;
            if (hk[1] > bvk) { bvk = hk[1]; bq = 1; }
            if (hk[2] > bvk) { bvk = hk[2]; bq = 2; }
            u64 rv = bvk;
            int rl = lane, rq = bq;
#pragma unroll
            for (int o = 16; o; o >>= 1) {
                u64 ov = __shfl_down_sync(0xffffffffu, rv, o);
                int ol = __shfl_down_sync(0xffffffffu, rl, o);
                int oq = __shfl_down_sync(0xffffffffu, rq, o);
                if (ov > rv) { rv = ov; rl = ol; rq = oq; }
            }
            rv = __shfl_sync(0xffffffffu, rv, 0);
            rl = __shfl_sync(0xffffffffu, rl, 0);
            rq = __shfl_sync(0xffffffffu, rq, 0);
            if (rv == 0ull) { nw = k; break; }
            if (lane == 0) {
                u32 flat = 0xFFFFFFFFu - (u32)rv;
                w_sc[k] = __uint_as_float((u32)(rv >> 32));
                w_an[k] = (int)(flat / NC);
                w_lab[k] = (int)(flat % NC);
            }
            if (lane == rl) {
                hj[rq]++;
                int c = lane + rq * 32;
                hk[rq] = (hj[rq] < MAXDET) ? skey[c * MAXDET + hj[rq]] : 0ull;
            }
        }
        if (lane == 0) s_nw = nw;
    }
    __syncthreads();

    int nw = s_nw;
    const float4* __restrict__ bb = (const float4*)(boxes + (size_t)b * NA * 4);
    float* ob = out + (size_t)b * MAXDET * 4;
    float* os = out + (size_t)NB * MAXDET * 4 + (size_t)b * MAXDET;
    float* ol = out + (size_t)NB * MAXDET * 5 + (size_t)b * MAXDET;

    if (t < MAXDET) {
        if (t < nw) {
            float4 bx = bb[w_an[t]];
            ob[t * 4 + 0] = bx.x;
            ob[t * 4 + 1] = bx.y;
            ob[t * 4 + 2] = bx.z;
            ob[t * 4 + 3] = bx.w;
            os[t] = w_sc[t];
            ol[t] = (float)w_lab[t];
        } else {
            ob[t * 4 + 0] = -1.0f;
            ob[t * 4 + 1] = -1.0f;
            ob[t * 4 + 2] = -1.0f;
            ob[t * 4 + 3] = -1.0f;
            os[t] = -1.0f;
            ol[t] = -1.0f;
        }
    }
}

// ---------------------------------------------------------------------------
extern "C" void kernel_launch(void* const* d_in, const int* in_sizes, int n_in,
                              void* d_out, int out_size)
{
    const float* boxes = (const float*)d_in[0];
    const float* cls   = (const float*)d_in[1];
    float* out = (float*)d_out;

    cudaFuncSetAttribute(fused_kernel, cudaFuncAttributeMaxDynamicSharedMemorySize, DYN_BYTES);
    cudaFuncSetAttribute(topk_kernel, cudaFuncAttributeMaxDynamicSharedMemorySize, TOPK_DYN);

    init_kernel<<<1, 512>>>();
    {
        dim3 grid((NC + 7) / 8, NB);
        gather_kernel<<<grid, TF>>>(cls);
    }
    fused_kernel<<<NPAIR, TF, DYN_BYTES>>>(boxes);
    fallback_kernel<<<NPAIR, T1>>>(boxes, cls);
    topk_kernel<<<NB, TT, TOPK_DYN>>>(boxes, out);
}

// round 5
// speedup vs baseline: 21.4456x; 2.2135x over previous
#include <cuda_runtime.h>
#include <cuda_bf16.h>

typedef unsigned long long u64;
typedef unsigned int u32;

#define NB 4
#define NA 49104
#define NC 90
#define MAXDET 100
#define NPAIR (NB * NC)
#define NEGV (-1e30f)
#define SCORE_THR 0.01f
#define IOU_THR 0.1f

// Candidate prefix: scores > T0 (uniform data -> ~4910 per pair)
#define T0 0.90f
#define NSH 8            // counter shards per pair
#define SCAP 768         // capacity per shard (mean ~614, >6 sigma margin)
#define CAP (NSH * SCAP) // 6144
#define NBIN 2048

#define TG 256           // gather block
#define TF2 256          // fused block
#define T1 1024          // fallback block
#define IPT 48

// ---------------- global scratch ----------------
__device__ u64  g_cand[(size_t)NPAIR * CAP];
__device__ int  g_cnt[NPAIR * NSH];
__device__ int  g_flag[NPAIR];
__device__ float g_ks[NPAIR * MAXDET];
__device__ int   g_ka[NPAIR * MAXDET];
__device__ int   g_kc[NPAIR];

// ---------------------------------------------------------------------------
__global__ void init_kernel()
{
    int idx = blockIdx.x * blockDim.x + threadIdx.x;
    if (idx < NPAIR * NSH) g_cnt[idx] = 0;
    if (idx < NPAIR) g_flag[idx] = 0;
}

// ---------------------------------------------------------------------------
// Gather: fully coalesced float2 scan of classification; sharded counters.
// ---------------------------------------------------------------------------
__device__ __forceinline__ void push_cand(int b, int c, int a, float s, int sh)
{
    int pair = b * NC + c;
    int pos = atomicAdd(&g_cnt[pair * NSH + sh], 1);
    if (pos < SCAP) {
        u64 key = ((u64)__float_as_uint(s) << 32) | (u32)(0xFFFFFFFFu - (u32)a);
        g_cand[(size_t)pair * CAP + sh * SCAP + pos] = key;
    }
}

__global__ __launch_bounds__(TG) void gather_kernel(const float* __restrict__ cls)
{
    const float2* __restrict__ p = (const float2*)cls;
    const u32 total = (u32)NB * NA * 45;       // float2 elements
    const u32 stride = gridDim.x * TG;
    const int sh = threadIdx.x & (NSH - 1);

    for (u32 idx = blockIdx.x * TG + threadIdx.x; idx < total; idx += stride) {
        float2 v = p[idx];
        if (v.x > T0 || v.y > T0) {
            u32 per = (u32)NA * 45;
            int b = idx / per;
            u32 r = idx - (u32)b * per;
            int a = r / 45;
            int c2 = (int)(r - (u32)a * 45) * 2;
            if (v.x > T0) push_cand(b, c2,     a, v.x, sh);
            if (v.y > T0) push_cand(b, c2 + 1, a, v.y, sh);
        }
    }
}

// ---------------------------------------------------------------------------
// Fused: counting-sort candidates (desc by (score, anchor asc)) + warp-batched
// greedy NMS with software-pipelined box loads. One CTA per pair, 3 CTAs/SM.
// ---------------------------------------------------------------------------
#define DYN_BYTES (CAP * 8 + NBIN * 4 * 2)

__global__ __launch_bounds__(TF2, 3) void fused_kernel(const float* __restrict__ boxes)
{
    const int pair = blockIdx.x;
    const int b = pair / NC;
    const float4* __restrict__ bb = (const float4*)(boxes + (size_t)b * NA * 4);
    const int t = threadIdx.x;

    extern __shared__ char dyn[];
    u64* skey     = (u64*)dyn;                   // CAP * 8
    u32* binstart = (u32*)(dyn + CAP * 8);       // NBIN * 4
    u32* bincnt   = binstart + NBIN;             // NBIN * 4

    __shared__ float4 kb[MAXDET];
    __shared__ float  karea[MAXDET];
    __shared__ float  ksc[MAXDET];
    __shared__ int    kan[MAXDET];
    __shared__ u32    warpsum[8];
    __shared__ int    s_cnt_sh[NSH];
    __shared__ int    s_kept, s_done, s_bad;

    if (t < NSH) {
        int c = g_cnt[pair * NSH + t];
        s_cnt_sh[t] = c;
        if (t == 0) s_bad = 0;
    }
    __syncthreads();
    if (t < NSH && s_cnt_sh[t] > SCAP) atomicExch(&s_bad, 1);
    for (int i = t; i < NBIN; i += TF2) bincnt[i] = 0;
    __syncthreads();
    if (s_bad) { if (t == 0) g_flag[pair] = 1; return; }

    const u64* __restrict__ cand = &g_cand[(size_t)pair * CAP];

    // histogram (bin index flipped for descending order)
#pragma unroll
    for (int sh = 0; sh < NSH; sh++) {
        int cs = s_cnt_sh[sh];
        for (int i = t; i < cs; i += TF2) {
            u64 k = cand[sh * SCAP + i];
            float s = __uint_as_float((u32)(k >> 32));
            int bin = (int)((s - T0) * 20480.0f);
            bin = min(max(bin, 0), NBIN - 1);
            atomicAdd(&bincnt[NBIN - 1 - bin], 1u);
        }
    }
    __syncthreads();

    // exclusive scan over NBIN bins (8 bins/thread, 8 warps)
    {
        u32 c[8];
        u32 tsum = 0;
#pragma unroll
        for (int q = 0; q < 8; q++) { c[q] = bincnt[8 * t + q]; tsum += c[q]; }
        u32 lane = t & 31, w = t >> 5;
        u32 x = tsum;
#pragma unroll
        for (int o = 1; o < 32; o <<= 1) {
            u32 y = __shfl_up_sync(0xffffffffu, x, o);
            if (lane >= (u32)o) x += y;
        }
        if (lane == 31) warpsum[w] = x;
        __syncthreads();
        if (t == 0) {
            u32 r = 0;
#pragma unroll
            for (int i2 = 0; i2 < 8; i2++) { u32 v = warpsum[i2]; warpsum[i2] = r; r += v; }
        }
        __syncthreads();
        u32 ex = warpsum[w] + x - tsum;
#pragma unroll
        for (int q = 0; q < 8; q++) { binstart[8 * t + q] = ex; ex += c[q]; }
    }
    __syncthreads();

    // scatter (binstart becomes end cursor)
    int cnt = 0;
#pragma unroll
    for (int sh = 0; sh < NSH; sh++) cnt += s_cnt_sh[sh];
#pragma unroll
    for (int sh = 0; sh < NSH; sh++) {
        int cs = s_cnt_sh[sh];
        for (int i = t; i < cs; i += TF2) {
            u64 k = cand[sh * SCAP + i];
            float s = __uint_as_float((u32)(k >> 32));
            int bin = (int)((s - T0) * 20480.0f);
            bin = min(max(bin, 0), NBIN - 1);
            u32 pos = atomicAdd(&binstart[NBIN - 1 - bin], 1u);
            skey[pos] = k;
        }
    }
    __syncthreads();

    // fix within-bin order (descending u64 => score desc, anchor asc)
    for (int bin = t; bin < NBIN; bin += TF2) {
        int c2 = (int)bincnt[bin];
        if (c2 >= 2) {
            int st = (int)binstart[bin] - c2;
            for (int x = st + 1; x < st + c2; x++) {
                u64 kk = skey[x];
                int y = x - 1;
                while (y >= st && skey[y] < kk) { skey[y + 1] = skey[y]; y--; }
                skey[y + 1] = kk;
            }
        }
    }
    if (t == 0) { s_kept = 0; s_done = 0; }
    __syncthreads();

    // greedy on warp 0: batches of 32, pipelined box loads, uniform kept-scan
    if (t < 32) {
        const int lane = t;
        int kept = 0;
        int i = 0;
        // preload batch 0
        bool act = lane < cnt;
        u64 k = act ? skey[lane] : 0ull;
        u32 anc = 0xFFFFFFFFu - (u32)k;
        float sc_ = __uint_as_float((u32)(k >> 32));
        float4 bx = act ? bb[anc] : make_float4(0.f, 0.f, 0.f, 0.f);

        while (kept < MAXDET && i < cnt) {
            // prefetch next batch (hides L2 latency behind kept-scan)
            int ni = i + 32;
            bool nact = (ni + lane) < cnt;
            u64 nk = nact ? skey[ni + lane] : 0ull;
            u32 nanc = 0xFFFFFFFFu - (u32)nk;
            float4 nbx = nact ? bb[nanc] : make_float4(0.f, 0.f, 0.f, 0.f);

            float barea = (bx.z - bx.x) * (bx.w - bx.y);
            bool ok = act;
            // warp-uniform scan of kept list, early-exit every 8
            int j = 0;
            while (j < kept) {
                int je = min(j + 8, kept);
                for (; j < je; j++) {
                    float4 s4 = kb[j];
                    float iy1 = fmaxf(s4.x, bx.x);
                    float ix1 = fmaxf(s4.y, bx.y);
                    float iy2 = fminf(s4.z, bx.z);
                    float ix2 = fminf(s4.w, bx.w);
                    float inter = fmaxf(iy2 - iy1, 0.0f) * fmaxf(ix2 - ix1, 0.0f);
                    float iou = inter / (karea[j] + barea - inter + 1e-8f);
                    if (iou > IOU_THR) ok = false;
                }
                if (!__any_sync(0xffffffffu, ok)) break;
            }
            u32 prov = __ballot_sync(0xffffffffu, ok);
            u32 m = prov;
            while (m && kept < MAXDET) {
                int l = __ffs(m) - 1;
                m &= m - 1;
                float ay1 = __shfl_sync(0xffffffffu, bx.x, l);
                float ax1 = __shfl_sync(0xffffffffu, bx.y, l);
                float ay2 = __shfl_sync(0xffffffffu, bx.z, l);
                float ax2 = __shfl_sync(0xffffffffu, bx.w, l);
                float asc = __shfl_sync(0xffffffffu, sc_, l);
                u32   aan = __shfl_sync(0xffffffffu, anc, l);
                float aarea = (ay2 - ay1) * (ax2 - ax1);
                if (lane == 0) {
                    kb[kept] = make_float4(ay1, ax1, ay2, ax2);
                    karea[kept] = aarea;
                    ksc[kept] = asc;
                    kan[kept] = (int)aan;
                }
                __syncwarp();
                kept++;
                if (kept >= MAXDET) break;
                // re-test later provisional candidates vs this accept
                bool fail = false;
                if (((prov >> lane) & 1u) && lane > l) {
                    float iy1 = fmaxf(ay1, bx.x);
                    float ix1 = fmaxf(ax1, bx.y);
                    float iy2 = fminf(ay2, bx.z);
                    float ix2 = fminf(ax2, bx.w);
                    float inter = fmaxf(iy2 - iy1, 0.0f) * fmaxf(ix2 - ix1, 0.0f);
                    float iou = inter / (aarea + barea - inter + 1e-8f);
                    if (iou > IOU_THR) fail = true;
                }
                u32 fm = __ballot_sync(0xffffffffu, fail);
                prov &= ~fm;
                m &= ~fm;
            }
            __syncwarp();
            i += 32;
            k = nk; anc = nanc; bx = nbx; act = nact;
            sc_ = __uint_as_float((u32)(nk >> 32));
        }
        if (lane == 0) { s_kept = kept; s_done = (kept >= MAXDET); }
    }
    __syncthreads();

    if (!s_done) { if (t == 0) g_flag[pair] = 1; return; }

    int kept = s_kept;
    if (t < kept) {
        g_ks[pair * MAXDET + t] = ksc[t];
        g_ka[pair * MAXDET + t] = kan[t];
    }
    if (t == 0) g_kc[pair] = kept;
}

// ---------------------------------------------------------------------------
// Fallback: full per-pair NMS, runs only for flagged pairs (expected: none).
// ---------------------------------------------------------------------------
__global__ __launch_bounds__(T1) void fallback_kernel(const float* __restrict__ boxes,
                                                      const float* __restrict__ cls)
{
    const int pair = blockIdx.x;
    if (!g_flag[pair]) return;
    const int b = pair / NC;
    const int c = pair % NC;
    const float4* __restrict__ bb = (const float4*)(boxes + (size_t)b * NA * 4);
    const float* __restrict__ sc = cls + (size_t)b * NA * NC + c;
    const int t = threadIdx.x;

    float s[IPT];
#pragma unroll
    for (int i = 0; i < IPT; i++) {
        int a = i * T1 + t;
        float v = (a < NA) ? sc[(size_t)a * NC] : NEGV;
        s[i] = (v > SCORE_THR) ? v : NEGV;
    }

    __shared__ float wv[32];
    __shared__ int   wi[32];
    __shared__ float sbox[4];
    __shared__ int   ssel;
    __shared__ float ks_s[MAXDET];
    __shared__ int   ka_s[MAXDET];
    __shared__ int   scnt;
    if (t == 0) scnt = 0;

    bool exhausted = false;

    for (int it = 0; it < MAXDET; it++) {
        float bv = NEGV;
        int   bi = 0x7FFFFFFF;
#pragma unroll
        for (int i = 0; i < IPT; i++) {
            if (s[i] > bv) { bv = s[i]; bi = i * T1 + t; }
        }
#pragma unroll
        for (int o = 16; o; o >>= 1) {
            float ov = __shfl_down_sync(0xffffffffu, bv, o);
            int   oi = __shfl_down_sync(0xffffffffu, bi, o);
            if (ov > bv || (ov == bv && oi < bi)) { bv = ov; bi = oi; }
        }
        if ((t & 31) == 0) { wv[t >> 5] = bv; wi[t >> 5] = bi; }
        __syncthreads();
        if (t < 32) {
            bv = wv[t]; bi = wi[t];
#pragma unroll
            for (int o = 16; o; o >>= 1) {
                float ov = __shfl_down_sync(0xffffffffu, bv, o);
                int   oi = __shfl_down_sync(0xffffffffu, bi, o);
                if (ov > bv || (ov == bv && oi < bi)) { bv = ov; bi = oi; }
            }
            if (t == 0) {
                if (bv > -0.5e30f) {
                    float4 bx = bb[bi];
                    sbox[0] = bx.x; sbox[1] = bx.y; sbox[2] = bx.z; sbox[3] = bx.w;
                    ssel = bi;
                    int k = scnt;
                    ks_s[k] = bv;
                    ka_s[k] = bi;
                    scnt = k + 1;
                } else {
                    ssel = -1;
                }
            }
        }
        __syncthreads();

        int sel = ssel;
        if (sel < 0) { exhausted = true; break; }

        float y1 = sbox[0], x1 = sbox[1], y2 = sbox[2], x2 = sbox[3];
        float sarea = (y2 - y1) * (x2 - x1);
#pragma unroll
        for (int i = 0; i < IPT; i++) {
            if (s[i] > -1e29f) {
                int a = i * T1 + t;
                float4 bx = bb[a];
                float iy1 = fmaxf(y1, bx.x);
                float ix1 = fmaxf(x1, bx.y);
                float iy2 = fminf(y2, bx.z);
                float ix2 = fminf(x2, bx.w);
                float inter = fmaxf(iy2 - iy1, 0.0f) * fmaxf(ix2 - ix1, 0.0f);
                float barea = (bx.z - bx.x) * (bx.w - bx.y);
                float iou = inter / (sarea + barea - inter + 1e-8f);
                if (iou > IOU_THR) s[i] = NEGV;
                if (a == sel)      s[i] = NEGV;
            }
        }
        __syncthreads();
    }

    __syncthreads();
    if (t == 0) {
        int cnt = scnt;
        if (exhausted) {
            for (int k = 0; k < cnt; k++) {
                if (ka_s[k] == 0) {
                    for (int m2 = k; m2 < cnt - 1; m2++) {
                        ks_s[m2] = ks_s[m2 + 1];
                        ka_s[m2] = ka_s[m2 + 1];
                    }
                    cnt--;
                    break;
                }
            }
            scnt = cnt;
        }
    }
    __syncthreads();
    int cnt = scnt;
    int base2 = pair * MAXDET;
    if (t < cnt) {
        g_ks[base2 + t] = ks_s[t];
        g_ka[base2 + t] = ka_s[t];
    }
    if (t == 0) g_kc[pair] = cnt;
}

// ---------------------------------------------------------------------------
// topk: 90-way merge of sorted kept lists. 1 CTA per image, merge on warp 0.
// ---------------------------------------------------------------------------
#define TT 256
#define TOPK_DYN (NC * MAXDET * 8)

__global__ __launch_bounds__(TT) void topk_kernel(const float* __restrict__ boxes,
                                                  float* __restrict__ out)
{
    const int b = blockIdx.x;
    const int t = threadIdx.x;

    extern __shared__ u64 skey[];   // NC*MAXDET

    __shared__ int   cnts[NC];
    __shared__ int   w_an[MAXDET];
    __shared__ float w_sc[MAXDET];
    __shared__ int   w_lab[MAXDET];
    __shared__ int   s_nw;

    if (t < NC) cnts[t] = g_kc[b * NC + t];
    __syncthreads();

    for (int i = t; i < NC * MAXDET; i += TT) {
        int c = i / MAXDET, j = i % MAXDET;
        u64 key = 0ull;
        if (j < cnts[c]) {
            int pb = (b * NC + c) * MAXDET + j;
            float sv = g_ks[pb];
            int   av = g_ka[pb];
            u32 flat = (u32)av * NC + (u32)c;
            key = ((u64)__float_as_uint(sv) << 32) | (0xFFFFFFFFu - flat);
        }
        skey[i] = key;
    }
    __syncthreads();

    if (t < 32) {
        const int lane = t;
        u64 hk[3];
        int hj[3];
#pragma unroll
        for (int q = 0; q < 3; q++) {
            int c = lane + q * 32;
            hj[q] = 0;
            hk[q] = (c < NC) ? skey[c * MAXDET] : 0ull;
        }
        int nw = MAXDET;
        for (int k = 0; k < MAXDET; k++) {
            u64 bvk = hk[0];
            int bq = 0;
            if (hk[1] > bvk) { bvk = hk[1]; bq = 1; }
            if (hk[2] > bvk) { bvk = hk[2]; bq = 2; }
            u64 rv = bvk;
            int rl = lane, rq = bq;
#pragma unroll
            for (int o = 16; o; o >>= 1) {
                u64 ov = __shfl_down_sync(0xffffffffu, rv, o);
                int ol = __shfl_down_sync(0xffffffffu, rl, o);
                int oq = __shfl_down_sync(0xffffffffu, rq, o);
                if (ov > rv) { rv = ov; rl = ol; rq = oq; }
            }
            rv = __shfl_sync(0xffffffffu, rv, 0);
            rl = __shfl_sync(0xffffffffu, rl, 0);
            rq = __shfl_sync(0xffffffffu, rq, 0);
            if (rv == 0ull) { nw = k; break; }
            if (lane == 0) {
                u32 flat = 0xFFFFFFFFu - (u32)rv;
                w_sc[k] = __uint_as_float((u32)(rv >> 32));
                w_an[k] = (int)(flat / NC);
                w_lab[k] = (int)(flat % NC);
            }
            if (lane == rl) {
                hj[rq]++;
                int c = lane + rq * 32;
                hk[rq] = (hj[rq] < MAXDET) ? skey[c * MAXDET + hj[rq]] : 0ull;
            }
        }
        if (lane == 0) s_nw = nw;
    }
    __syncthreads();

    int nw = s_nw;
    const float4* __restrict__ bb = (const float4*)(boxes + (size_t)b * NA * 4);
    float* ob = out + (size_t)b * MAXDET * 4;
    float* os = out + (size_t)NB * MAXDET * 4 + (size_t)b * MAXDET;
    float* ol = out + (size_t)NB * MAXDET * 5 + (size_t)b * MAXDET;

    if (t < MAXDET) {
        if (t < nw) {
            float4 bx = bb[w_an[t]];
            ob[t * 4 + 0] = bx.x;
            ob[t * 4 + 1] = bx.y;
            ob[t * 4 + 2] = bx.z;
            ob[t * 4 + 3] = bx.w;
            os[t] = w_sc[t];
            ol[t] = (float)w_lab[t];
        } else {
            ob[t * 4 + 0] = -1.0f;
            ob[t * 4 + 1] = -1.0f;
            ob[t * 4 + 2] = -1.0f;
            ob[t * 4 + 3] = -1.0f;
            os[t] = -1.0f;
            ol[t] = -1.0f;
        }
    }
}

// ---------------------------------------------------------------------------
extern "C" void kernel_launch(void* const* d_in, const int* in_sizes, int n_in,
                              void* d_out, int out_size)
{
    const float* boxes = (const float*)d_in[0];
    const float* cls   = (const float*)d_in[1];
    float* out = (float*)d_out;

    cudaFuncSetAttribute(fused_kernel, cudaFuncAttributeMaxDynamicSharedMemorySize, DYN_BYTES);
    cudaFuncSetAttribute(topk_kernel, cudaFuncAttributeMaxDynamicSharedMemorySize, TOPK_DYN);

    init_kernel<<<8, 512>>>();
    gather_kernel<<<4416, TG>>>(cls);
    fused_kernel<<<NPAIR, TF2, DYN_BYTES>>>(boxes);
    fallback_kernel<<<NPAIR, T1>>>(boxes, cls);
    topk_kernel<<<NB, TT, TOPK_DYN>>>(boxes, out);
}

// round 6
// speedup vs baseline: 29.3757x; 1.3698x over previous
#include <cuda_runtime.h>
#include <cuda_bf16.h>

typedef unsigned long long u64;
typedef unsigned int u32;

#define NB 4
#define NA 49104
#define NC 90
#define MAXDET 100
#define NPAIR (NB * NC)
#define NEGV (-1e30f)
#define SCORE_THR 0.01f
#define IOU_THR 0.1f

// Candidate prefix: scores > T0 (uniform data -> ~4910 per pair)
#define T0 0.90f
#define NSH 8            // counter shards per pair
#define SCAP 768         // capacity per shard (mean ~614, >6 sigma margin)
#define CAP (NSH * SCAP) // 6144
#define NBIN 2048

#define TG 256           // gather block
#define TF2 256          // fused block
#define T1 1024          // fallback block
#define IPT 48

// ---------------- global scratch ----------------
__device__ u64  g_cand[(size_t)NPAIR * CAP];
__device__ int  g_cnt[NPAIR * NSH];
__device__ int  g_flag[NPAIR];
__device__ float g_ks[NPAIR * MAXDET];
__device__ int   g_ka[NPAIR * MAXDET];
__device__ int   g_kc[NPAIR];

// ---------------------------------------------------------------------------
__global__ void init_kernel()
{
    int idx = blockIdx.x * blockDim.x + threadIdx.x;
    if (idx < NPAIR * NSH) g_cnt[idx] = 0;
    if (idx < NPAIR) g_flag[idx] = 0;
}

// ---------------------------------------------------------------------------
// Gather: fully coalesced float4 scan of classification; sharded counters.
// ---------------------------------------------------------------------------
__device__ __forceinline__ void push_cand(u32 flat, float s, int sh)
{
    const u32 per = (u32)NA * NC;
    int b = flat / per;
    u32 r = flat - (u32)b * per;
    int a = r / NC;
    int c = (int)(r - (u32)a * NC);
    int pair = b * NC + c;
    int pos = atomicAdd(&g_cnt[pair * NSH + sh], 1);
    if (pos < SCAP) {
        u64 key = ((u64)__float_as_uint(s) << 32) | (u32)(0xFFFFFFFFu - (u32)a);
        g_cand[(size_t)pair * CAP + sh * SCAP + pos] = key;
    }
}

__global__ __launch_bounds__(TG) void gather_kernel(const float* __restrict__ cls)
{
    const float4* __restrict__ p = (const float4*)cls;
    const u32 total = ((u32)NB * NA * NC) / 4;   // float4 elements (divisible)
    const u32 stride = gridDim.x * TG;
    const int sh = threadIdx.x & (NSH - 1);

    for (u32 idx = blockIdx.x * TG + threadIdx.x; idx < total; idx += stride) {
        float4 v = p[idx];
        float mx = fmaxf(fmaxf(v.x, v.y), fmaxf(v.z, v.w));
        if (mx > T0) {
            u32 flat = idx * 4u;
            if (v.x > T0) push_cand(flat + 0u, v.x, sh);
            if (v.y > T0) push_cand(flat + 1u, v.y, sh);
            if (v.z > T0) push_cand(flat + 2u, v.z, sh);
            if (v.w > T0) push_cand(flat + 3u, v.w, sh);
        }
    }
}

// ---------------------------------------------------------------------------
// Fused: counting-sort candidates (desc by (score, anchor asc)) + cooperative
// greedy NMS: 8 warps share the kept-list scan, warp 0 does the serial fixup.
// One CTA per pair, 3 CTAs/SM.
// ---------------------------------------------------------------------------
#define DYN_BYTES (CAP * 8 + NBIN * 4 * 2)

__global__ __launch_bounds__(TF2, 3) void fused_kernel(const float* __restrict__ boxes)
{
    const int pair = blockIdx.x;
    const int b = pair / NC;
    const float4* __restrict__ bb = (const float4*)(boxes + (size_t)b * NA * 4);
    const int t = threadIdx.x;

    extern __shared__ char dyn[];
    u64* skey     = (u64*)dyn;                   // CAP * 8
    u32* binstart = (u32*)(dyn + CAP * 8);       // NBIN * 4
    u32* bincnt   = binstart + NBIN;             // NBIN * 4

    __shared__ float4 kb[MAXDET];
    __shared__ float  karea[MAXDET];
    __shared__ float  ksc[MAXDET];
    __shared__ int    kan[MAXDET];
    __shared__ u32    warpsum[8];
    __shared__ u32    sm_ok[8];
    __shared__ int    s_cnt_sh[NSH];
    __shared__ int    s_keptw, s_bad;

    if (t < NSH) {
        int c = g_cnt[pair * NSH + t];
        s_cnt_sh[t] = c;
        if (t == 0) s_bad = 0;
    }
    __syncthreads();
    if (t < NSH && s_cnt_sh[t] > SCAP) atomicExch(&s_bad, 1);
    for (int i = t; i < NBIN; i += TF2) bincnt[i] = 0;
    __syncthreads();
    if (s_bad) { if (t == 0) g_flag[pair] = 1; return; }

    const u64* __restrict__ cand = &g_cand[(size_t)pair * CAP];

    // histogram (bin index flipped for descending order)
#pragma unroll
    for (int sh = 0; sh < NSH; sh++) {
        int cs = s_cnt_sh[sh];
        for (int i = t; i < cs; i += TF2) {
            u64 k = cand[sh * SCAP + i];
            float s = __uint_as_float((u32)(k >> 32));
            int bin = (int)((s - T0) * 20480.0f);
            bin = min(max(bin, 0), NBIN - 1);
            atomicAdd(&bincnt[NBIN - 1 - bin], 1u);
        }
    }
    __syncthreads();

    // exclusive scan over NBIN bins (8 bins/thread, 8 warps)
    {
        u32 c[8];
        u32 tsum = 0;
#pragma unroll
        for (int q = 0; q < 8; q++) { c[q] = bincnt[8 * t + q]; tsum += c[q]; }
        u32 lane = t & 31, w = t >> 5;
        u32 x = tsum;
#pragma unroll
        for (int o = 1; o < 32; o <<= 1) {
            u32 y = __shfl_up_sync(0xffffffffu, x, o);
            if (lane >= (u32)o) x += y;
        }
        if (lane == 31) warpsum[w] = x;
        __syncthreads();
        if (t == 0) {
            u32 r = 0;
#pragma unroll
            for (int i2 = 0; i2 < 8; i2++) { u32 v = warpsum[i2]; warpsum[i2] = r; r += v; }
        }
        __syncthreads();
        u32 ex = warpsum[w] + x - tsum;
#pragma unroll
        for (int q = 0; q < 8; q++) { binstart[8 * t + q] = ex; ex += c[q]; }
    }
    __syncthreads();

    // scatter (binstart becomes end cursor)
    int cnt = 0;
#pragma unroll
    for (int sh = 0; sh < NSH; sh++) cnt += s_cnt_sh[sh];
#pragma unroll
    for (int sh = 0; sh < NSH; sh++) {
        int cs = s_cnt_sh[sh];
        for (int i = t; i < cs; i += TF2) {
            u64 k = cand[sh * SCAP + i];
            float s = __uint_as_float((u32)(k >> 32));
            int bin = (int)((s - T0) * 20480.0f);
            bin = min(max(bin, 0), NBIN - 1);
            u32 pos = atomicAdd(&binstart[NBIN - 1 - bin], 1u);
            skey[pos] = k;
        }
    }
    __syncthreads();

    // fix within-bin order (descending u64 => score desc, anchor asc)
    for (int bin = t; bin < NBIN; bin += TF2) {
        int c2 = (int)bincnt[bin];
        if (c2 >= 2) {
            int st = (int)binstart[bin] - c2;
            for (int x = st + 1; x < st + c2; x++) {
                u64 kk = skey[x];
                int y = x - 1;
                while (y >= st && skey[y] < kk) { skey[y + 1] = skey[y]; y--; }
                skey[y + 1] = kk;
            }
        }
    }
    if (t == 0) s_keptw = 0;
    __syncthreads();

    // ---- cooperative greedy: candidate = t&31, kept-slice = t>>5 ----
    {
        const int lane = t & 31;
        const int wrp  = t >> 5;
        int i = 0;
        for (;;) {
            int kept = s_keptw;                 // valid: barrier at loop tail
            if (kept >= MAXDET || i >= cnt) break;

            int idx = i + lane;
            bool act = idx < cnt;
            u64 k = act ? skey[idx] : 0ull;
            u32 anc = 0xFFFFFFFFu - (u32)k;
            float4 bx = act ? bb[anc] : make_float4(0.f, 0.f, 0.f, 0.f);
            float barea = (bx.z - bx.x) * (bx.w - bx.y);

            // stride-8 slice of the kept list per warp (<=13 IOU evals)
            bool ok = act;
            for (int j = wrp; j < kept; j += 8) {
                float4 s4 = kb[j];
                float iy1 = fmaxf(s4.x, bx.x);
                float ix1 = fmaxf(s4.y, bx.y);
                float iy2 = fminf(s4.z, bx.z);
                float ix2 = fminf(s4.w, bx.w);
                float inter = fmaxf(iy2 - iy1, 0.0f) * fmaxf(ix2 - ix1, 0.0f);
                float iou = inter / (karea[j] + barea - inter + 1e-8f);
                if (iou > IOU_THR) ok = false;
            }
            u32 wm = __ballot_sync(0xffffffffu, ok);
            if (lane == 0) sm_ok[wrp] = wm;
            __syncthreads();

            if (wrp == 0) {
                float sc_ = __uint_as_float((u32)(k >> 32));
                u32 prov = sm_ok[0] & sm_ok[1] & sm_ok[2] & sm_ok[3] &
                           sm_ok[4] & sm_ok[5] & sm_ok[6] & sm_ok[7];
                u32 m = prov;
                while (m && kept < MAXDET) {
                    int l = __ffs(m) - 1;
                    m &= m - 1;
                    float ay1 = __shfl_sync(0xffffffffu, bx.x, l);
                    float ax1 = __shfl_sync(0xffffffffu, bx.y, l);
                    float ay2 = __shfl_sync(0xffffffffu, bx.z, l);
                    float ax2 = __shfl_sync(0xffffffffu, bx.w, l);
                    float asc = __shfl_sync(0xffffffffu, sc_, l);
                    u32   aan = __shfl_sync(0xffffffffu, anc, l);
                    float aarea = (ay2 - ay1) * (ax2 - ax1);
                    if (lane == 0) {
                        kb[kept] = make_float4(ay1, ax1, ay2, ax2);
                        karea[kept] = aarea;
                        ksc[kept] = asc;
                        kan[kept] = (int)aan;
                    }
                    __syncwarp();
                    kept++;
                    if (kept >= MAXDET) break;
                    // re-test later provisional candidates vs this accept
                    bool fail = false;
                    if (((prov >> lane) & 1u) && lane > l) {
                        float iy1 = fmaxf(ay1, bx.x);
                        float ix1 = fmaxf(ax1, bx.y);
                        float iy2 = fminf(ay2, bx.z);
                        float ix2 = fminf(ax2, bx.w);
                        float inter = fmaxf(iy2 - iy1, 0.0f) * fmaxf(ix2 - ix1, 0.0f);
                        float iou = inter / (aarea + barea - inter + 1e-8f);
                        if (iou > IOU_THR) fail = true;
                    }
                    u32 fm = __ballot_sync(0xffffffffu, fail);
                    prov &= ~fm;
                    m &= ~fm;
                }
                if (lane == 0) s_keptw = kept;
            }
            i += 32;
            __syncthreads();   // publish s_keptw + kb updates before next scan
        }
    }
    __syncthreads();

    int kept = s_keptw;
    if (kept < MAXDET) { if (t == 0) g_flag[pair] = 1; return; }

    if (t < kept) {
        g_ks[pair * MAXDET + t] = ksc[t];
        g_ka[pair * MAXDET + t] = kan[t];
    }
    if (t == 0) g_kc[pair] = kept;
}

// ---------------------------------------------------------------------------
// Fallback: full per-pair NMS, runs only for flagged pairs (expected: none).
// ---------------------------------------------------------------------------
__global__ __launch_bounds__(T1) void fallback_kernel(const float* __restrict__ boxes,
                                                      const float* __restrict__ cls)
{
    const int pair = blockIdx.x;
    if (!g_flag[pair]) return;
    const int b = pair / NC;
    const int c = pair % NC;
    const float4* __restrict__ bb = (const float4*)(boxes + (size_t)b * NA * 4);
    const float* __restrict__ sc = cls + (size_t)b * NA * NC + c;
    const int t = threadIdx.x;

    float s[IPT];
#pragma unroll
    for (int i = 0; i < IPT; i++) {
        int a = i * T1 + t;
        float v = (a < NA) ? sc[(size_t)a * NC] : NEGV;
        s[i] = (v > SCORE_THR) ? v : NEGV;
    }

    __shared__ float wv[32];
    __shared__ int   wi[32];
    __shared__ float sbox[4];
    __shared__ int   ssel;
    __shared__ float ks_s[MAXDET];
    __shared__ int   ka_s[MAXDET];
    __shared__ int   scnt;
    if (t == 0) scnt = 0;

    bool exhausted = false;

    for (int it = 0; it < MAXDET; it++) {
        float bv = NEGV;
        int   bi = 0x7FFFFFFF;
#pragma unroll
        for (int i = 0; i < IPT; i++) {
            if (s[i] > bv) { bv = s[i]; bi = i * T1 + t; }
        }
#pragma unroll
        for (int o = 16; o; o >>= 1) {
            float ov = __shfl_down_sync(0xffffffffu, bv, o);
            int   oi = __shfl_down_sync(0xffffffffu, bi, o);
            if (ov > bv || (ov == bv && oi < bi)) { bv = ov; bi = oi; }
        }
        if ((t & 31) == 0) { wv[t >> 5] = bv; wi[t >> 5] = bi; }
        __syncthreads();
        if (t < 32) {
            bv = wv[t]; bi = wi[t];
#pragma unroll
            for (int o = 16; o; o >>= 1) {
                float ov = __shfl_down_sync(0xffffffffu, bv, o);
                int   oi = __shfl_down_sync(0xffffffffu, bi, o);
                if (ov > bv || (ov == bv && oi < bi)) { bv = ov; bi = oi; }
            }
            if (t == 0) {
                if (bv > -0.5e30f) {
                    float4 bx = bb[bi];
                    sbox[0] = bx.x; sbox[1] = bx.y; sbox[2] = bx.z; sbox[3] = bx.w;
                    ssel = bi;
                    int k = scnt;
                    ks_s[k] = bv;
                    ka_s[k] = bi;
                    scnt = k + 1;
                } else {
                    ssel = -1;
                }
            }
        }
        __syncthreads();

        int sel = ssel;
        if (sel < 0) { exhausted = true; break; }

        float y1 = sbox[0], x1 = sbox[1], y2 = sbox[2], x2 = sbox[3];
        float sarea = (y2 - y1) * (x2 - x1);
#pragma unroll
        for (int i = 0; i < IPT; i++) {
            if (s[i] > -1e29f) {
                int a = i * T1 + t;
                float4 bx = bb[a];
                float iy1 = fmaxf(y1, bx.x);
                float ix1 = fmaxf(x1, bx.y);
                float iy2 = fminf(y2, bx.z);
                float ix2 = fminf(x2, bx.w);
                float inter = fmaxf(iy2 - iy1, 0.0f) * fmaxf(ix2 - ix1, 0.0f);
                float barea = (bx.z - bx.x) * (bx.w - bx.y);
                float iou = inter / (sarea + barea - inter + 1e-8f);
                if (iou > IOU_THR) s[i] = NEGV;
                if (a == sel)      s[i] = NEGV;
            }
        }
        __syncthreads();
    }

    __syncthreads();
    if (t == 0) {
        int cnt = scnt;
        if (exhausted) {
            for (int k = 0; k < cnt; k++) {
                if (ka_s[k] == 0) {
                    for (int m2 = k; m2 < cnt - 1; m2++) {
                        ks_s[m2] = ks_s[m2 + 1];
                        ka_s[m2] = ka_s[m2 + 1];
                    }
                    cnt--;
                    break;
                }
            }
            scnt = cnt;
        }
    }
    __syncthreads();
    int cnt = scnt;
    int base2 = pair * MAXDET;
    if (t < cnt) {
        g_ks[base2 + t] = ks_s[t];
        g_ka[base2 + t] = ka_s[t];
    }
    if (t == 0) g_kc[pair] = cnt;
}

// ---------------------------------------------------------------------------
// topk: 90-way merge of sorted kept lists. 1 CTA per image, merge on warp 0.
// ---------------------------------------------------------------------------
#define TT 256
#define TOPK_DYN (NC * MAXDET * 8)

__global__ __launch_bounds__(TT) void topk_kernel(const float* __restrict__ boxes,
                                                  float* __restrict__ out)
{
    const int b = blockIdx.x;
    const int t = threadIdx.x;

    extern __shared__ u64 skey[];   // NC*MAXDET

    __shared__ int   cnts[NC];
    __shared__ int   w_an[MAXDET];
    __shared__ float w_sc[MAXDET];
    __shared__ int   w_lab[MAXDET];
    __shared__ int   s_nw;

    if (t < NC) cnts[t] = g_kc[b * NC + t];
    __syncthreads();

    for (int i = t; i < NC * MAXDET; i += TT) {
        int c = i / MAXDET, j = i % MAXDET;
        u64 key = 0ull;
        if (j < cnts[c]) {
            int pb = (b * NC + c) * MAXDET + j;
            float sv = g_ks[pb];
            int   av = g_ka[pb];
            u32 flat = (u32)av * NC + (u32)c;
            key = ((u64)__float_as_uint(sv) << 32) | (0xFFFFFFFFu - flat);
        }
        skey[i] = key;
    }
    __syncthreads();

    if (t < 32) {
        const int lane = t;
        u64 hk[3];
        int hj[3];
#pragma unroll
        for (int q = 0; q < 3; q++) {
            int c = lane + q * 32;
            hj[q] = 0;
            hk[q] = (c < NC) ? skey[c * MAXDET] : 0ull;
        }
        int nw = MAXDET;
        for (int k = 0; k < MAXDET; k++) {
            u64 bvk = hk[0];
            int bq = 0;
            if (hk[1] > bvk) { bvk = hk[1]; bq = 1; }
            if (hk[2] > bvk) { bvk = hk[2]; bq = 2; }
            u64 rv = bvk;
            int rl = lane, rq = bq;
#pragma unroll
            for (int o = 16; o; o >>= 1) {
                u64 ov = __shfl_down_sync(0xffffffffu, rv, o);
                int ol = __shfl_down_sync(0xffffffffu, rl, o);
                int oq = __shfl_down_sync(0xffffffffu, rq, o);
                if (ov > rv) { rv = ov; rl = ol; rq = oq; }
            }
            rv = __shfl_sync(0xffffffffu, rv, 0);
            rl = __shfl_sync(0xffffffffu, rl, 0);
            rq = __shfl_sync(0xffffffffu, rq, 0);
            if (rv == 0ull) { nw = k; break; }
            if (lane == 0) {
                u32 flat = 0xFFFFFFFFu - (u32)rv;
                w_sc[k] = __uint_as_float((u32)(rv >> 32));
                w_an[k] = (int)(flat / NC);
                w_lab[k] = (int)(flat % NC);
            }
            if (lane == rl) {
                hj[rq]++;
                int c = lane + rq * 32;
                hk[rq] = (hj[rq] < MAXDET) ? skey[c * MAXDET + hj[rq]] : 0ull;
            }
        }
        if (lane == 0) s_nw = nw;
    }
    __syncthreads();

    int nw = s_nw;
    const float4* __restrict__ bb = (const float4*)(boxes + (size_t)b * NA * 4);
    float* ob = out + (size_t)b * MAXDET * 4;
    float* os = out + (size_t)NB * MAXDET * 4 + (size_t)b * MAXDET;
    float* ol = out + (size_t)NB * MAXDET * 5 + (size_t)b * MAXDET;

    if (t < MAXDET) {
        if (t < nw) {
            float4 bx = bb[w_an[t]];
            ob[t * 4 + 0] = bx.x;
            ob[t * 4 + 1] = bx.y;
            ob[t * 4 + 2] = bx.z;
            ob[t * 4 + 3] = bx.w;
            os[t] = w_sc[t];
            ol[t] = (float)w_lab[t];
        } else {
            ob[t * 4 + 0] = -1.0f;
            ob[t * 4 + 1] = -1.0f;
            ob[t * 4 + 2] = -1.0f;
            ob[t * 4 + 3] = -1.0f;
            os[t] = -1.0f;
            ol[t] = -1.0f;
        }
    }
}

// ---------------------------------------------------------------------------
extern "C" void kernel_launch(void* const* d_in, const int* in_sizes, int n_in,
                              void* d_out, int out_size)
{
    const float* boxes = (const float*)d_in[0];
    const float* cls   = (const float*)d_in[1];
    float* out = (float*)d_out;

    cudaFuncSetAttribute(fused_kernel, cudaFuncAttributeMaxDynamicSharedMemorySize, DYN_BYTES);
    cudaFuncSetAttribute(topk_kernel, cudaFuncAttributeMaxDynamicSharedMemorySize, TOPK_DYN);

    init_kernel<<<8, 512>>>();
    gather_kernel<<<2160, TG>>>(cls);
    fused_kernel<<<NPAIR, TF2, DYN_BYTES>>>(boxes);
    fallback_kernel<<<NPAIR, T1>>>(boxes, cls);
    topk_kernel<<<NB, TT, TOPK_DYN>>>(boxes, out);
}

// round 7
// speedup vs baseline: 32.3150x; 1.1001x over previous
#include <cuda_runtime.h>
#include <cuda_bf16.h>

typedef unsigned long long u64;
typedef unsigned int u32;

#define NB 4
#define NA 49104
#define NC 90
#define MAXDET 100
#define NPAIR (NB * NC)
#define NEGV (-1e30f)
#define SCORE_THR 0.01f
#define IOU_THR 0.1f

// Candidate prefix: scores > T0 (uniform data -> ~4910 per pair)
#define T0 0.90f
#define NSH 8            // counter shards per pair
#define SCAP 768         // capacity per shard (mean ~614, >6 sigma margin)
#define CAP (NSH * SCAP) // 6144
#define NBIN 2048

#define TG 256           // gather block
#define TF2 256          // fused block
#define T1 1024          // fallback block
#define IPT 48

// ---------------- global scratch ----------------
__device__ u64  g_cand[(size_t)NPAIR * CAP];
__device__ int  g_cnt[NPAIR * NSH];
__device__ int  g_flag[NPAIR];
__device__ float g_ks[NPAIR * MAXDET];
__device__ int   g_ka[NPAIR * MAXDET];
__device__ int   g_kc[NPAIR];

// ---------------------------------------------------------------------------
__global__ void init_kernel()
{
    int idx = blockIdx.x * blockDim.x + threadIdx.x;
    if (idx < NPAIR * NSH) g_cnt[idx] = 0;
    if (idx < NPAIR) g_flag[idx] = 0;
}

// ---------------------------------------------------------------------------
// Gather: fully coalesced float4 scan of classification; sharded counters.
// ---------------------------------------------------------------------------
__device__ __forceinline__ void push_cand(u32 flat, float s, int sh)
{
    const u32 per = (u32)NA * NC;
    int b = flat / per;
    u32 r = flat - (u32)b * per;
    int a = r / NC;
    int c = (int)(r - (u32)a * NC);
    int pair = b * NC + c;
    int pos = atomicAdd(&g_cnt[pair * NSH + sh], 1);
    if (pos < SCAP) {
        u64 key = ((u64)__float_as_uint(s) << 32) | (u32)(0xFFFFFFFFu - (u32)a);
        g_cand[(size_t)pair * CAP + sh * SCAP + pos] = key;
    }
}

__global__ __launch_bounds__(TG) void gather_kernel(const float* __restrict__ cls)
{
    const float4* __restrict__ p = (const float4*)cls;
    const u32 total = ((u32)NB * NA * NC) / 4;   // float4 elements (divisible)
    const u32 stride = gridDim.x * TG;
    const int sh = threadIdx.x & (NSH - 1);

    for (u32 idx = blockIdx.x * TG + threadIdx.x; idx < total; idx += stride) {
        float4 v = p[idx];
        float mx = fmaxf(fmaxf(v.x, v.y), fmaxf(v.z, v.w));
        if (mx > T0) {
            u32 flat = idx * 4u;
            if (v.x > T0) push_cand(flat + 0u, v.x, sh);
            if (v.y > T0) push_cand(flat + 1u, v.y, sh);
            if (v.z > T0) push_cand(flat + 2u, v.z, sh);
            if (v.w > T0) push_cand(flat + 3u, v.w, sh);
        }
    }
}

// ---------------------------------------------------------------------------
// Fused: counting-sort candidates (desc by (score, anchor asc)) + cooperative
// greedy NMS with software-pipelined box loads. 8 warps share the kept-list
// scan, warp 0 does the serial fixup. One CTA per pair, 3 CTAs/SM.
// ---------------------------------------------------------------------------
#define DYN_BYTES (CAP * 8 + NBIN * 4 * 2)

__global__ __launch_bounds__(TF2, 3) void fused_kernel(const float* __restrict__ boxes)
{
    const int pair = blockIdx.x;
    const int b = pair / NC;
    const float4* __restrict__ bb = (const float4*)(boxes + (size_t)b * NA * 4);
    const int t = threadIdx.x;

    extern __shared__ char dyn[];
    u64* skey     = (u64*)dyn;                   // CAP * 8
    u32* binstart = (u32*)(dyn + CAP * 8);       // NBIN * 4
    u32* bincnt   = binstart + NBIN;             // NBIN * 4

    __shared__ float4 kb[MAXDET];
    __shared__ float  karea[MAXDET];
    __shared__ float  ksc[MAXDET];
    __shared__ int    kan[MAXDET];
    __shared__ u32    warpsum[8];
    __shared__ u32    sm_ok[8];
    __shared__ int    s_cnt_sh[NSH];
    __shared__ int    s_keptw, s_bad;

    if (t < NSH) {
        int c = g_cnt[pair * NSH + t];
        s_cnt_sh[t] = c;
        if (t == 0) s_bad = 0;
    }
    __syncthreads();
    if (t < NSH && s_cnt_sh[t] > SCAP) atomicExch(&s_bad, 1);
    for (int i = t; i < NBIN; i += TF2) bincnt[i] = 0;
    __syncthreads();
    if (s_bad) { if (t == 0) g_flag[pair] = 1; return; }

    const u64* __restrict__ cand = &g_cand[(size_t)pair * CAP];

    // histogram (bin index flipped for descending order)
#pragma unroll
    for (int sh = 0; sh < NSH; sh++) {
        int cs = s_cnt_sh[sh];
        for (int i = t; i < cs; i += TF2) {
            u64 k = cand[sh * SCAP + i];
            float s = __uint_as_float((u32)(k >> 32));
            int bin = (int)((s - T0) * 20480.0f);
            bin = min(max(bin, 0), NBIN - 1);
            atomicAdd(&bincnt[NBIN - 1 - bin], 1u);
        }
    }
    __syncthreads();

    // exclusive scan over NBIN bins (8 bins/thread, 8 warps)
    {
        u32 c[8];
        u32 tsum = 0;
#pragma unroll
        for (int q = 0; q < 8; q++) { c[q] = bincnt[8 * t + q]; tsum += c[q]; }
        u32 lane = t & 31, w = t >> 5;
        u32 x = tsum;
#pragma unroll
        for (int o = 1; o < 32; o <<= 1) {
            u32 y = __shfl_up_sync(0xffffffffu, x, o);
            if (lane >= (u32)o) x += y;
        }
        if (lane == 31) warpsum[w] = x;
        __syncthreads();
        if (t == 0) {
            u32 r = 0;
#pragma unroll
            for (int i2 = 0; i2 < 8; i2++) { u32 v = warpsum[i2]; warpsum[i2] = r; r += v; }
        }
        __syncthreads();
        u32 ex = warpsum[w] + x - tsum;
#pragma unroll
        for (int q = 0; q < 8; q++) { binstart[8 * t + q] = ex; ex += c[q]; }
    }
    __syncthreads();

    // scatter (binstart becomes end cursor)
    int cnt = 0;
#pragma unroll
    for (int sh = 0; sh < NSH; sh++) cnt += s_cnt_sh[sh];
#pragma unroll
    for (int sh = 0; sh < NSH; sh++) {
        int cs = s_cnt_sh[sh];
        for (int i = t; i < cs; i += TF2) {
            u64 k = cand[sh * SCAP + i];
            float s = __uint_as_float((u32)(k >> 32));
            int bin = (int)((s - T0) * 20480.0f);
            bin = min(max(bin, 0), NBIN - 1);
            u32 pos = atomicAdd(&binstart[NBIN - 1 - bin], 1u);
            skey[pos] = k;
        }
    }
    __syncthreads();

    // fix within-bin order (descending u64 => score desc, anchor asc)
    for (int bin = t; bin < NBIN; bin += TF2) {
        int c2 = (int)bincnt[bin];
        if (c2 >= 2) {
            int st = (int)binstart[bin] - c2;
            for (int x = st + 1; x < st + c2; x++) {
                u64 kk = skey[x];
                int y = x - 1;
                while (y >= st && skey[y] < kk) { skey[y + 1] = skey[y]; y--; }
                skey[y + 1] = kk;
            }
        }
    }
    if (t == 0) s_keptw = 0;
    __syncthreads();

    // ---- cooperative greedy with prefetch: candidate = t&31, slice = t>>5 ----
    {
        const int lane = t & 31;
        const int wrp  = t >> 5;
        int i = 0;
        // preload batch 0
        bool act = lane < cnt;
        u64 k = act ? skey[lane] : 0ull;
        u32 anc = 0xFFFFFFFFu - (u32)k;
        float4 bx = act ? bb[anc] : make_float4(0.f, 0.f, 0.f, 0.f);

        for (;;) {
            int kept = s_keptw;                 // valid: barrier at loop tail
            if (kept >= MAXDET || i >= cnt) break;

            // prefetch batch i+32 (hides L2 latency behind the kept-scan)
            int nidx = i + 32 + lane;
            bool nact = nidx < cnt;
            u64 nk = nact ? skey[nidx] : 0ull;
            u32 nanc = 0xFFFFFFFFu - (u32)nk;
            float4 nbx = nact ? bb[nanc] : make_float4(0.f, 0.f, 0.f, 0.f);

            float barea = (bx.z - bx.x) * (bx.w - bx.y);

            // stride-8 slice of the kept list per warp (<=13 IOU evals)
            bool ok = act;
            for (int j = wrp; j < kept; j += 8) {
                float4 s4 = kb[j];
                float iy1 = fmaxf(s4.x, bx.x);
                float ix1 = fmaxf(s4.y, bx.y);
                float iy2 = fminf(s4.z, bx.z);
                float ix2 = fminf(s4.w, bx.w);
                float inter = fmaxf(iy2 - iy1, 0.0f) * fmaxf(ix2 - ix1, 0.0f);
                float iou = inter / (karea[j] + barea - inter + 1e-8f);
                if (iou > IOU_THR) ok = false;
            }
            u32 wm = __ballot_sync(0xffffffffu, ok);
            if (lane == 0) sm_ok[wrp] = wm;
            __syncthreads();

            if (wrp == 0) {
                float sc_ = __uint_as_float((u32)(k >> 32));
                u32 prov = sm_ok[0] & sm_ok[1] & sm_ok[2] & sm_ok[3] &
                           sm_ok[4] & sm_ok[5] & sm_ok[6] & sm_ok[7];
                u32 m = prov;
                while (m && kept < MAXDET) {
                    int l = __ffs(m) - 1;
                    m &= m - 1;
                    float ay1 = __shfl_sync(0xffffffffu, bx.x, l);
                    float ax1 = __shfl_sync(0xffffffffu, bx.y, l);
                    float ay2 = __shfl_sync(0xffffffffu, bx.z, l);
                    float ax2 = __shfl_sync(0xffffffffu, bx.w, l);
                    float asc = __shfl_sync(0xffffffffu, sc_, l);
                    u32   aan = __shfl_sync(0xffffffffu, anc, l);
                    float aarea = (ay2 - ay1) * (ax2 - ax1);
                    if (lane == 0) {
                        kb[kept] = make_float4(ay1, ax1, ay2, ax2);
                        karea[kept] = aarea;
                        ksc[kept] = asc;
                        kan[kept] = (int)aan;
                    }
                    __syncwarp();
                    kept++;
                    if (kept >= MAXDET) break;
                    // re-test later provisional candidates vs this accept
                    bool fail = false;
                    if (((prov >> lane) & 1u) && lane > l) {
                        float iy1 = fmaxf(ay1, bx.x);
                        float ix1 = fmaxf(ax1, bx.y);
                        float iy2 = fminf(ay2, bx.z);
                        float ix2 = fminf(ax2, bx.w);
                        float inter = fmaxf(iy2 - iy1, 0.0f) * fmaxf(ix2 - ix1, 0.0f);
                        float iou = inter / (aarea + barea - inter + 1e-8f);
                        if (iou > IOU_THR) fail = true;
                    }
                    u32 fm = __ballot_sync(0xffffffffu, fail);
                    prov &= ~fm;
                    m &= ~fm;
                }
                if (lane == 0) s_keptw = kept;
            }
            i += 32;
            __syncthreads();   // publish s_keptw + kb updates before next scan
            k = nk; anc = nanc; bx = nbx; act = nact;
        }
    }
    __syncthreads();

    int kept = s_keptw;
    if (kept < MAXDET) { if (t == 0) g_flag[pair] = 1; return; }

    if (t < kept) {
        g_ks[pair * MAXDET + t] = ksc[t];
        g_ka[pair * MAXDET + t] = kan[t];
    }
    if (t == 0) g_kc[pair] = kept;
}

// ---------------------------------------------------------------------------
// Fallback: full per-pair NMS, persistent grid-stride over flagged pairs
// (expected: none flagged).
// ---------------------------------------------------------------------------
__global__ __launch_bounds__(T1) void fallback_kernel(const float* __restrict__ boxes,
                                                      const float* __restrict__ cls)
{
    const int t = threadIdx.x;

    __shared__ float wv[32];
    __shared__ int   wi[32];
    __shared__ float sbox[4];
    __shared__ int   ssel;
    __shared__ float ks_s[MAXDET];
    __shared__ int   ka_s[MAXDET];
    __shared__ int   scnt;

    for (int pair = blockIdx.x; pair < NPAIR; pair += gridDim.x) {
        __syncthreads();                 // separate iterations
        if (!g_flag[pair]) continue;     // uniform per block

        const int b = pair / NC;
        const int c = pair % NC;
        const float4* __restrict__ bb = (const float4*)(boxes + (size_t)b * NA * 4);
        const float* __restrict__ sc = cls + (size_t)b * NA * NC + c;

        float s[IPT];
#pragma unroll
        for (int i = 0; i < IPT; i++) {
            int a = i * T1 + t;
            float v = (a < NA) ? sc[(size_t)a * NC] : NEGV;
            s[i] = (v > SCORE_THR) ? v : NEGV;
        }

        if (t == 0) scnt = 0;

        bool exhausted = false;

        for (int it = 0; it < MAXDET; it++) {
            float bv = NEGV;
            int   bi = 0x7FFFFFFF;
#pragma unroll
            for (int i = 0; i < IPT; i++) {
                if (s[i] > bv) { bv = s[i]; bi = i * T1 + t; }
            }
#pragma unroll
            for (int o = 16; o; o >>= 1) {
                float ov = __shfl_down_sync(0xffffffffu, bv, o);
                int   oi = __shfl_down_sync(0xffffffffu, bi, o);
                if (ov > bv || (ov == bv && oi < bi)) { bv = ov; bi = oi; }
            }
            if ((t & 31) == 0) { wv[t >> 5] = bv; wi[t >> 5] = bi; }
            __syncthreads();
            if (t < 32) {
                bv = wv[t]; bi = wi[t];
#pragma unroll
                for (int o = 16; o; o >>= 1) {
                    float ov = __shfl_down_sync(0xffffffffu, bv, o);
                    int   oi = __shfl_down_sync(0xffffffffu, bi, o);
                    if (ov > bv || (ov == bv && oi < bi)) { bv = ov; bi = oi; }
                }
                if (t == 0) {
                    if (bv > -0.5e30f) {
                        float4 bx = bb[bi];
                        sbox[0] = bx.x; sbox[1] = bx.y; sbox[2] = bx.z; sbox[3] = bx.w;
                        ssel = bi;
                        int k = scnt;
                        ks_s[k] = bv;
                        ka_s[k] = bi;
                        scnt = k + 1;
                    } else {
                        ssel = -1;
                    }
                }
            }
            __syncthreads();

            int sel = ssel;
            if (sel < 0) { exhausted = true; break; }

            float y1 = sbox[0], x1 = sbox[1], y2 = sbox[2], x2 = sbox[3];
            float sarea = (y2 - y1) * (x2 - x1);
#pragma unroll
            for (int i = 0; i < IPT; i++) {
                if (s[i] > -1e29f) {
                    int a = i * T1 + t;
                    float4 bx = bb[a];
                    float iy1 = fmaxf(y1, bx.x);
                    float ix1 = fmaxf(x1, bx.y);
                    float iy2 = fminf(y2, bx.z);
                    float ix2 = fminf(x2, bx.w);
                    float inter = fmaxf(iy2 - iy1, 0.0f) * fmaxf(ix2 - ix1, 0.0f);
                    float barea = (bx.z - bx.x) * (bx.w - bx.y);
                    float iou = inter / (sarea + barea - inter + 1e-8f);
                    if (iou > IOU_THR) s[i] = NEGV;
                    if (a == sel)      s[i] = NEGV;
                }
            }
            __syncthreads();
        }

        __syncthreads();
        if (t == 0) {
            int cnt = scnt;
            if (exhausted) {
                for (int k = 0; k < cnt; k++) {
                    if (ka_s[k] == 0) {
                        for (int m2 = k; m2 < cnt - 1; m2++) {
                            ks_s[m2] = ks_s[m2 + 1];
                            ka_s[m2] = ka_s[m2 + 1];
                        }
                        cnt--;
                        break;
                    }
                }
                scnt = cnt;
            }
        }
        __syncthreads();
        int cnt = scnt;
        int base2 = pair * MAXDET;
        if (t < cnt) {
            g_ks[base2 + t] = ks_s[t];
            g_ka[base2 + t] = ka_s[t];
        }
        if (t == 0) g_kc[pair] = cnt;
    }
}

// ---------------------------------------------------------------------------
// topk: 90-way merge of sorted kept lists. 1 CTA per image, merge on warp 0.
// ---------------------------------------------------------------------------
#define TT 512
#define TOPK_DYN (NC * MAXDET * 8)

__global__ __launch_bounds__(TT) void topk_kernel(const float* __restrict__ boxes,
                                                  float* __restrict__ out)
{
    const int b = blockIdx.x;
    const int t = threadIdx.x;

    extern __shared__ u64 skey[];   // NC*MAXDET

    __shared__ int   cnts[NC];
    __shared__ int   w_an[MAXDET];
    __shared__ float w_sc[MAXDET];
    __shared__ int   w_lab[MAXDET];
    __shared__ int   s_nw;

    if (t < NC) cnts[t] = g_kc[b * NC + t];
    __syncthreads();

    for (int i = t; i < NC * MAXDET; i += TT) {
        int c = i / MAXDET, j = i % MAXDET;
        u64 key = 0ull;
        if (j < cnts[c]) {
            int pb = (b * NC + c) * MAXDET + j;
            float sv = g_ks[pb];
            int   av = g_ka[pb];
            u32 flat = (u32)av * NC + (u32)c;
            key = ((u64)__float_as_uint(sv) << 32) | (0xFFFFFFFFu - flat);
        }
        skey[i] = key;
    }
    __syncthreads();

    if (t < 32) {
        const int lane = t;
        u64 hk[3];
        int hj[3];
#pragma unroll
        for (int q = 0; q < 3; q++) {
            int c = lane + q * 32;
            hj[q] = 0;
            hk[q] = (c < NC) ? skey[c * MAXDET] : 0ull;
        }
        int nw = MAXDET;
        for (int k = 0; k < MAXDET; k++) {
            u64 bvk = hk[0];
            int bq = 0;
            if (hk[1] > bvk) { bvk = hk[1]; bq = 1; }
            if (hk[2] > bvk) { bvk = hk[2]; bq = 2; }
            u64 rv = bvk;
            int rl = lane, rq = bq;
#pragma unroll
            for (int o = 16; o; o >>= 1) {
                u64 ov = __shfl_down_sync(0xffffffffu, rv, o);
                int ol = __shfl_down_sync(0xffffffffu, rl, o);
                int oq = __shfl_down_sync(0xffffffffu, rq, o);
                if (ov > rv) { rv = ov; rl = ol; rq = oq; }
            }
            rv = __shfl_sync(0xffffffffu, rv, 0);
            rl = __shfl_sync(0xffffffffu, rl, 0);
            rq = __shfl_sync(0xffffffffu, rq, 0);
            if (rv == 0ull) { nw = k; break; }
            if (lane == 0) {
                u32 flat = 0xFFFFFFFFu - (u32)rv;
                w_sc[k] = __uint_as_float((u32)(rv >> 32));
                w_an[k] = (int)(flat / NC);
                w_lab[k] = (int)(flat % NC);
            }
            if (lane == rl) {
                hj[rq]++;
                int c = lane + rq * 32;
                hk[rq] = (hj[rq] < MAXDET) ? skey[c * MAXDET + hj[rq]] : 0ull;
            }
        }
        if (lane == 0) s_nw = nw;
    }
    __syncthreads();

    int nw = s_nw;
    const float4* __restrict__ bb = (const float4*)(boxes + (size_t)b * NA * 4);
    float* ob = out + (size_t)b * MAXDET * 4;
    float* os = out + (size_t)NB * MAXDET * 4 + (size_t)b * MAXDET;
    float* ol = out + (size_t)NB * MAXDET * 5 + (size_t)b * MAXDET;

    if (t < MAXDET) {
        if (t < nw) {
            float4 bx = bb[w_an[t]];
            ob[t * 4 + 0] = bx.x;
            ob[t * 4 + 1] = bx.y;
            ob[t * 4 + 2] = bx.z;
            ob[t * 4 + 3] = bx.w;
            os[t] = w_sc[t];
            ol[t] = (float)w_lab[t];
        } else {
            ob[t * 4 + 0] = -1.0f;
            ob[t * 4 + 1] = -1.0f;
            ob[t * 4 + 2] = -1.0f;
            ob[t * 4 + 3] = -1.0f;
            os[t] = -1.0f;
            ol[t] = -1.0f;
        }
    }
}

// ---------------------------------------------------------------------------
extern "C" void kernel_launch(void* const* d_in, const int* in_sizes, int n_in,
                              void* d_out, int out_size)
{
    const float* boxes = (const float*)d_in[0];
    const float* cls   = (const float*)d_in[1];
    float* out = (float*)d_out;

    cudaFuncSetAttribute(fused_kernel, cudaFuncAttributeMaxDynamicSharedMemorySize, DYN_BYTES);
    cudaFuncSetAttribute(topk_kernel, cudaFuncAttributeMaxDynamicSharedMemorySize, TOPK_DYN);

    init_kernel<<<8, 512>>>();
    gather_kernel<<<2160, TG>>>(cls);
    fused_kernel<<<NPAIR, TF2, DYN_BYTES>>>(boxes);
    fallback_kernel<<<148, T1>>>(boxes, cls);
    topk_kernel<<<NB, TT, TOPK_DYN>>>(boxes, out);
}